// round 6
// baseline (speedup 1.0000x reference)
#include <cuda_runtime.h>
#include <math.h>

#define DPI 3.14159265358979323846

#define NB   128
#define NIN  30
#define BB1  10
#define MM1  19
#define NA1  20
#define FF1  20
#define BB2  6
#define MM2  11
#define NA2  12
#define FF2  40
#define FOUT 10
#define P1   24
#define P2   144

// ---- constant tables ----
__device__ float  gWS2F[BB1*MM1*NIN];
__device__ float2 gT1t[NIN*NIN*BB1*MM1];           // [kj][lm]
__device__ float2 gBS2[P1*BB1*MM1];
__device__ float  gWINV1[NA1*BB1*MM1*MM1];
__device__ float2 gEA1[MM1*NA1];
__device__ float  gWSO3[NA1*BB2*MM2*MM2];
__device__ float2 gF20[MM2*NA1];
__device__ float2 gBSO3[P2*BB2*MM2*MM2];
__device__ float  gWINV2[NA2*BB2*MM2*MM2];
__device__ float2 gEA2[MM2*NA2];
__device__ float  gWINT[NA2];

// ---- init helper tables ----
__device__ float  gQW15[30];
__device__ float  gQW10[20];
__device__ float2 gPA8[8*19];
__device__ float2 gPA8b[8*11];
__device__ float2 gPG6[6*11];
__device__ float2 gPH30[19*30];
__device__ float  gDS2G[3*10*10];
__device__ float  gDG3[3*6*121];

// ---- scratch ----
#define XCH 6
#define XLEN 150
__device__ float2 gXpart[XCH][NB*BB1*MM1];
__device__ float2 gX   [NB*BB1*MM1];
__device__ float2 gPSI [FF1*BB1*MM1];
__device__ float2 gX2  [NB*FF1*BB2*MM2*MM2];
__device__ float2 gPSI2[FF1*FF2*BB2*MM2*MM2];
__device__ float2 gZ2  [NB*FF2*BB2*MM2*MM2];       // invalid (l,m,n) stay 0 forever
__device__ float  gFEAT[NB*FF2];

__device__ __constant__ double c_fact[21] = {
  1.0, 1.0, 2.0, 6.0, 24.0, 120.0, 720.0, 5040.0, 40320.0, 362880.0,
  3628800.0, 39916800.0, 479001600.0, 6227020800.0, 87178291200.0,
  1307674368000.0, 20922789888000.0, 355687428096000.0,
  6402373705728000.0, 121645100408832000.0, 2432902008176640000.0 };

__device__ __forceinline__ double ipowd(double x, int e) {
  double r = 1.0;
  for (int i = 0; i < e; ++i) r *= x;
  return r;
}

__device__ double wigd(int l, int m, int n, double beta) {
  double cb = cos(0.5 * beta), sb = sin(0.5 * beta);
  double pref = sqrt(c_fact[l+m] * c_fact[l-m] * c_fact[l+n] * c_fact[l-n]);
  int s0 = (n - m > 0) ? (n - m) : 0;
  int s1 = (l + n < l - m) ? (l + n) : (l - m);
  double v = 0.0;
  for (int s = s0; s <= s1; ++s) {
    double t = 1.0 / (c_fact[l+n-s] * c_fact[s] * c_fact[m-n+s] * c_fact[l-m-s]);
    if ((m - n + s) & 1) t = -t;
    v += t * ipowd(cb, 2*l + n - m - 2*s) * ipowd(sb, m - n + 2*s);
  }
  return pref * v;
}

__device__ double quadw(int b, int k) {
  double beta = DPI * (2*k + 1) / (4.0 * b);
  double s = 0.0;
  for (int j = 0; j < b; ++j) s += sin((2*j + 1) * beta) / (2*j + 1);
  return 2.0 / b * sin(beta) * s;
}

// ======================= init kernels =======================
__global__ void k_init_misc() {
  const int TOT = 30 + 20 + 12 + 152 + 88 + 66 + 570 + 380 + 132 + 220;
  for (int idx = blockIdx.x * blockDim.x + threadIdx.x; idx < TOT;
       idx += gridDim.x * blockDim.x) {
    int r = idx;
    if (r < 30) { gQW15[r] = (float)quadw(15, r); continue; }
    r -= 30;
    if (r < 20) { gQW10[r] = (float)quadw(10, r); continue; }
    r -= 20;
    if (r < 12) { gWINT[r] = (float)quadw(6, r); continue; }
    r -= 12;
    if (r < 152) {
      int ia = r / 19, mp = r % 19 - 9;
      double ph = -(double)mp * (2.0 * DPI * ia / 8.0);
      double s, c; sincos(ph, &s, &c);
      gPA8[r] = make_float2((float)c, (float)s); continue;
    }
    r -= 152;
    if (r < 88) {
      int ia = r / 11, mp = r % 11 - 5;
      double ph = -(double)mp * (2.0 * DPI * ia / 8.0);
      double s, c; sincos(ph, &s, &c);
      gPA8b[r] = make_float2((float)c, (float)s); continue;
    }
    r -= 88;
    if (r < 66) {
      int ig = r / 11, np = r % 11 - 5;
      double ph = -(double)np * (2.0 * DPI * ig / 6.0);
      double s, c; sincos(ph, &s, &c);
      gPG6[r] = make_float2((float)c, (float)s); continue;
    }
    r -= 66;
    if (r < 570) {
      int mp = r / 30 - 9, j = r % 30;
      double ph = -2.0 * DPI * (double)mp * j / 30.0;
      double s, c; sincos(ph, &s, &c);
      gPH30[r] = make_float2((float)c, (float)s); continue;
    }
    r -= 570;
    if (r < 380) {
      int m = r / 20 - 9, a = r % 20;
      double ph = (double)m * 2.0 * DPI * a / 20.0;
      double s, c; sincos(ph, &s, &c);
      gEA1[r] = make_float2((float)c, (float)s); continue;
    }
    r -= 380;
    if (r < 132) {
      int m = r / 12 - 5, a = r % 12;
      double ph = (double)m * 2.0 * DPI * a / 12.0;
      double s, c; sincos(ph, &s, &c);
      gEA2[r] = make_float2((float)c, (float)s); continue;
    }
    r -= 132;
    {
      int mu = r / 20 - 5, a = r % 20;
      double ph = -2.0 * DPI * (double)mu * a / 20.0;
      double s, c; sincos(ph, &s, &c);
      gF20[r] = make_float2((float)c, (float)s);
    }
  }
}

__global__ void k_init_wig() {
  int idx = blockIdx.x * blockDim.x + threadIdx.x;
  if (idx < 1650) {
    int kb = idx / 55, j = idx % 55;
    int l = 0; while (j >= l + 1) { j -= l + 1; ++l; }
    int mm = j;
    double beta = DPI * (2*kb + 1) / 60.0;
    double v = wigd(l, mm, 0, beta) * (double)gQW15[kb];
    gWS2F[(l*19 + 9 + mm)*30 + kb] = (float)v;
    gWS2F[(l*19 + 9 - mm)*30 + kb] = (mm & 1) ? (float)(-v) : (float)v;
    return;
  }
  idx -= 1650;
  if (idx < 165) {
    int ib = idx / 55, j = idx % 55;
    int l = 0; while (j >= l + 1) { j -= l + 1; ++l; }
    int mm = j;
    double beta = (ib + 1) * DPI / 24.0;
    gDS2G[(ib*10 + l)*10 + mm] = (float)wigd(l, mm, 0, beta);
    return;
  }
  idx -= 165;
  if (idx < 7700) {
    int k = idx / 385, j = idx % 385;
    int l = 0; while (j >= (l+1)*(l+1)) { j -= (l+1)*(l+1); ++l; }
    int mm = (int)sqrtf((float)j);
    while (mm*mm > j) --mm;
    while ((mm+1)*(mm+1) <= j) ++mm;
    int nn = j - mm*mm - mm;
    double beta = DPI * (2*k + 1) / 40.0;
    float fv = (float)(wigd(l, mm, nn, beta) * (2*l + 1));
    float sv = ((mm - nn) & 1) ? -fv : fv;
    float* W = &gWINV1[(k*10 + l)*361];
    W[(9+mm)*19 + (9+nn)] = fv;
    W[(9+nn)*19 + (9+mm)] = sv;
    W[(9-mm)*19 + (9-nn)] = sv;
    W[(9-nn)*19 + (9-mm)] = fv;
    return;
  }
  idx -= 7700;
  if (idx < 1092) {
    int k = idx / 91, j = idx % 91;
    int l = 0; while (j >= (l+1)*(l+1)) { j -= (l+1)*(l+1); ++l; }
    int mm = (int)sqrtf((float)j);
    while (mm*mm > j) --mm;
    while ((mm+1)*(mm+1) <= j) ++mm;
    int nn = j - mm*mm - mm;
    double beta = DPI * (2*k + 1) / 24.0;
    float fv = (float)(wigd(l, mm, nn, beta) * (2*l + 1));
    float sv = ((mm - nn) & 1) ? -fv : fv;
    float* W = &gWINV2[(k*6 + l)*121];
    W[(5+mm)*11 + (5+nn)] = fv;
    W[(5+nn)*11 + (5+mm)] = sv;
    W[(5-mm)*11 + (5-nn)] = sv;
    W[(5-nn)*11 + (5-mm)] = fv;
    return;
  }
  idx -= 1092;
  if (idx < 273) {
    int ib = idx / 91, j = idx % 91;
    int l = 0; while (j >= (l+1)*(l+1)) { j -= (l+1)*(l+1); ++l; }
    int mm = (int)sqrtf((float)j);
    while (mm*mm > j) --mm;
    while ((mm+1)*(mm+1) <= j) ++mm;
    int nn = j - mm*mm - mm;
    double beta = (ib + 1) * DPI / 24.0;
    float fv = (float)wigd(l, mm, nn, beta);
    float sv = ((mm - nn) & 1) ? -fv : fv;
    float* W = &gDG3[(ib*6 + l)*121];
    W[(5+mm)*11 + (5+nn)] = fv;
    W[(5+nn)*11 + (5+mm)] = sv;
    W[(5-mm)*11 + (5-nn)] = sv;
    W[(5-nn)*11 + (5-mm)] = fv;
  }
}

__global__ void k_init_fill() {
  const int TOT = 4560 + 14520 + 104544 + 171000;
  for (int idx = blockIdx.x * blockDim.x + threadIdx.x; idx < TOT;
       idx += gridDim.x * blockDim.x) {
    int r = idx;
    if (r < 4560) {
      int p = r / 190, lm = r % 190, l = lm / 19, m = lm % 19, mp = m - 9;
      float2 v = make_float2(0.f, 0.f);
      if (abs(mp) <= l) {
        int ib = p / 8, ia = p % 8;
        float d;
        if (mp >= 0) d = gDS2G[(ib*10 + l)*10 + mp];
        else {
          d = gDS2G[(ib*10 + l)*10 - mp];
          if ((-mp) & 1) d = -d;
        }
        float2 ph = gPA8[ia*19 + 9 + mp];
        v = make_float2(d * ph.x, d * ph.y);
      }
      gBS2[r] = v; continue;
    }
    r -= 4560;
    if (r < 14520) {
      int k = r / 726, l = (r / 121) % 6, m = (r / 11) % 11, n = r % 11;
      float w = gWINV1[(k*10 + l)*361 + (m + 4)*19 + (n + 4)];
      gWSO3[r] = w * gQW10[k] / (float)(2*l + 1); continue;
    }
    r -= 14520;
    if (r < 104544) {
      int p = r / 726, l = (r / 121) % 6, m = (r / 11) % 11, n = r % 11;
      int ib = p / 48, ia = (p / 6) % 8, ig = p % 6;
      float d = gDG3[(ib*6 + l)*121 + m*11 + n];
      float2 pa = gPA8b[ia*11 + m], pg = gPG6[ig*11 + n];
      float2 ph = make_float2(pa.x*pg.x - pa.y*pg.y, pa.x*pg.y + pa.y*pg.x);
      gBSO3[r] = make_float2(d * ph.x, d * ph.y); continue;
    }
    r -= 104544;
    {
      int lm = r / 900, kj = r % 900;
      int k = kj / 30, j = kj % 30;
      int mp = (lm % 19) - 9;
      float w = gWS2F[lm*30 + k];
      float2 ph = gPH30[(mp + 9)*30 + j];
      gT1t[kj*190 + lm] = make_float2(w * ph.x, w * ph.y);
    }
  }
}

// ======================= pipeline =======================
// X partial: block = b*XCH + chunk, each chunk covers XLEN kj
__global__ void k_x_part(const float* __restrict__ x) {
  __shared__ float xs[XLEN];
  int blk = blockIdx.x;
  int c = blk % XCH, b = blk / XCH;
  for (int i = threadIdx.x; i < XLEN; i += blockDim.x) xs[i] = x[b*900 + c*XLEN + i];
  __syncthreads();
  int t = threadIdx.x;
  if (t < 190) {
    float re = 0.f, im = 0.f;
    const float2* T = &gT1t[c * XLEN * 190];
#pragma unroll 5
    for (int i = 0; i < XLEN; ++i) {
      float xv = xs[i];
      float2 w = T[i * 190 + t];
      re += xv * w.x; im += xv * w.y;
    }
    gXpart[c][b*190 + t] = make_float2(re, im);
  }
}

__global__ void k_x_comb() {
  int idx = blockIdx.x * blockDim.x + threadIdx.x;
  if (idx >= NB*190) return;
  float re = 0.f, im = 0.f;
#pragma unroll
  for (int c = 0; c < XCH; ++c) {
    float2 v = gXpart[c][idx];
    re += v.x; im += v.y;
  }
  gX[idx] = make_float2(re, im);
}

__global__ void k_psi(const float* __restrict__ k1) {
  int idx = blockIdx.x * blockDim.x + threadIdx.x;
  if (idx >= FF1*BB1*MM1) return;
  int lm = idx % 190, o = idx / 190;
  float re = 0.f, im = 0.f;
  for (int p = 0; p < P1; ++p) {
    float kv = k1[o*P1 + p];
    float2 bv = gBS2[p*190 + lm];
    re += kv * bv.x; im += kv * bv.y;
  }
  gPSI[idx] = make_float2(re, im);
}

// ---- fused stage 1 v2: one block per (b,o); k-loop inside; X2 accumulated in smem ----
__global__ __launch_bounds__(256) void k_fused1() {
  __shared__ float2 sP[BB1*361];   // [l][m][n] = X[l,m]*conj(psi[l,n])  (28880 B)
  __shared__ float2 sX2a[726];     // [l][mn] accumulator                (5808 B)
  __shared__ float2 sYK[121];      // ymn for current k                  (968 B)
  __shared__ float2 sEA1[380];     // (3040 B)
  __shared__ float2 sF20[220];     // (1760 B)
  __shared__ float2 sFH[190];      // [mi][n], m=9+mi                    (1520 B)
  __shared__ float2 sT[200];       // [mi][g]                            (1600 B)
  __shared__ float  sY[400];       // [a][g]                             (1600 B)
  __shared__ float2 sU[120];       // [r][g], mu=5+r                     (960 B)

  int blk = blockIdx.x;            // b*FF1 + o
  int o = blk % FF1, b = blk / FF1;
  int tid = threadIdx.x;

  // stage X into sFH, psi into sT (reused later)
  for (int e = tid; e < 190; e += 256) { sFH[e] = gX[b*190 + e]; sT[e] = gPSI[o*190 + e]; }
  for (int e = tid; e < 380; e += 256) sEA1[e] = gEA1[e];
  for (int e = tid; e < 220; e += 256) sF20[e] = gF20[e];
  for (int e = tid; e < 726; e += 256) sX2a[e] = make_float2(0.f, 0.f);
  __syncthreads();

  // P[l][m][n] = X[l,m] * conj(psi[l,n])
  for (int e = tid; e < 3610; e += 256) {
    int l = e / 361, mn = e % 361, m = mn / 19, n = mn % 19;
    float2 xm = sFH[l*19 + m];
    float2 pe = sT[l*19 + n];
    sP[e] = make_float2(xm.x*pe.x + xm.y*pe.y, xm.y*pe.x - xm.x*pe.y);
  }
  __syncthreads();

  for (int k = 0; k < NA1; ++k) {
    // fh[mi][n] = sum_{l>=lmin} W[k,l,9+mi,n] * P[l,9+mi,n]
    const float* W = &gWINV1[k * BB1 * 361];
    for (int e = tid; e < 190; e += 256) {
      int mi = e / 19, n = e % 19;
      int an = n - 9; if (an < 0) an = -an;
      int lmin = mi > an ? mi : an;
      int off = (9 + mi)*19 + n;
      float re = 0.f, im = 0.f;
      for (int l = lmin; l < BB1; ++l) {
        float w = W[l*361 + off];
        float2 p = sP[l*361 + off];
        re += w * p.x; im += w * p.y;
      }
      sFH[e] = make_float2(re, im);
    }
    __syncthreads();

    // t[mi][g] = sum_n fh[mi][n] * EA1[n][g]
    for (int e = tid; e < 200; e += 256) {
      int mi = e / 20, g = e % 20;
      float re = 0.f, im = 0.f;
#pragma unroll
      for (int n = 0; n < 19; ++n) {
        float2 f = sFH[mi*19 + n];
        float2 ea = sEA1[n*20 + g];
        re += f.x * ea.x - f.y * ea.y;
        im += f.x * ea.y + f.y * ea.x;
      }
      sT[e] = make_float2(re, im);
    }
    __syncthreads();

    // y[a][g] = Re t[0][g] + 2 sum_{mm=1..9} Re(t[mm][g]*EA1[9+mm][a])
    for (int e = tid; e < 400; e += 256) {
      int a = e / 20, g = e % 20;
      float v = sT[g].x;
      float acc = 0.f;
#pragma unroll
      for (int mm = 1; mm < 10; ++mm) {
        float2 t = sT[mm*20 + g];
        float2 ea = sEA1[(9 + mm)*20 + a];
        acc += t.x * ea.x - t.y * ea.y;
      }
      v += 2.f * acc;
      sY[e] = (v > 0.f) ? v : 0.f;
    }
    __syncthreads();

    // u[r][g] = sum_a y[a][g] * F20[5+r][a]
    for (int e = tid; e < 120; e += 256) {
      int r = e / 20, g = e % 20;
      float re = 0.f, im = 0.f;
#pragma unroll
      for (int a = 0; a < 20; ++a) {
        float yv = sY[a*20 + g];
        float2 f = sF20[(5 + r)*20 + a];
        re += yv * f.x; im += yv * f.y;
      }
      sU[e] = make_float2(re, im);
    }
    __syncthreads();

    // ymn[5+r][nu] + hermitian mirror into sYK
    for (int e = tid; e < 66; e += 256) {
      int r = e / 11, nu = e % 11;
      float re = 0.f, im = 0.f;
#pragma unroll
      for (int g = 0; g < 20; ++g) {
        float2 u = sU[r*20 + g];
        float2 f = sF20[nu*20 + g];
        re += u.x * f.x - u.y * f.y;
        im += u.x * f.y + u.y * f.x;
      }
      sYK[(5 + r)*11 + nu] = make_float2(re, im);
      if (r > 0) sYK[(5 - r)*11 + (10 - nu)] = make_float2(re, -im);
    }
    __syncthreads();

    // X2 accumulation: X2[l][mn] += WSO3[k,l,mn] * ymn[mn]
    const float* WS = &gWSO3[k * 726];
    for (int e = tid; e < 726; e += 256) {
      float w = WS[e];
      float2 yk = sYK[e % 121];
      sX2a[e].x += w * yk.x;
      sX2a[e].y += w * yk.y;
    }
    __syncthreads();
  }

  // write X2
  long base = (long)blk * 726;
  for (int e = tid; e < 726; e += 256) gX2[base + e] = sX2a[e];
}

// psi2 as real x complex GEMM: (800 x 144) x (144 x 726)
__global__ void k_psi2(const float* __restrict__ k2) {
  const int M = 800, N = 726, K = 144;
  __shared__ float As[32][17];
  __shared__ __align__(16) float2 Bs[16][34];
  int tx = threadIdx.x, ty = threadIdx.y;
  int tid = ty * 16 + tx;
  int row0 = blockIdx.y * 32, col0 = blockIdx.x * 32;
  float2 c00 = {0.f,0.f}, c01 = {0.f,0.f}, c10 = {0.f,0.f}, c11 = {0.f,0.f};

  for (int kt = 0; kt < K; kt += 16) {
#pragma unroll
    for (int e = tid; e < 512; e += 256) {
      int i = e >> 4, kq = e & 15;
      int row = row0 + i, kc = kt + kq;
      As[i][kq] = (row < M) ? k2[row*K + kc] : 0.f;
    }
#pragma unroll
    for (int e = tid; e < 512; e += 256) {
      int kq = e >> 5, j = e & 31;
      int kc = kt + kq, col = col0 + j;
      Bs[kq][j] = (col < N) ? gBSO3[kc*726 + col] : make_float2(0.f, 0.f);
    }
    __syncthreads();
#pragma unroll
    for (int kq = 0; kq < 16; ++kq) {
      float a0 = As[ty*2][kq];
      float a1 = As[ty*2 + 1][kq];
      float4 bb = *reinterpret_cast<const float4*>(&Bs[kq][tx*2]);
      c00.x += a0*bb.x; c00.y += a0*bb.y;
      c01.x += a0*bb.z; c01.y += a0*bb.w;
      c10.x += a1*bb.x; c10.y += a1*bb.y;
      c11.x += a1*bb.z; c11.y += a1*bb.w;
    }
    __syncthreads();
  }
  int r0 = row0 + ty*2, cc0 = col0 + tx*2;
  if (r0 < M) {
    if (cc0 < N)     gPSI2[r0*726 + cc0] = c00;
    if (cc0 + 1 < N) gPSI2[r0*726 + cc0 + 1] = c01;
  }
  if (r0 + 1 < M) {
    if (cc0 < N)     gPSI2[(r0+1)*726 + cc0] = c10;
    if (cc0 + 1 < N) gPSI2[(r0+1)*726 + cc0 + 1] = c11;
  }
}

// Z2 complex GEMM per l, compacted to valid (2l+1) ranges.
__global__ void k_z2() {
  int l = blockIdx.z;
  int D = 2*l + 1;
  int R = 128*D, C = 40*D, K = 20*D;
  int row0 = blockIdx.y * 32, col0 = blockIdx.x * 32;
  if (row0 >= R || col0 >= C) return;
  __shared__ __align__(16) float2 As[32][17];
  __shared__ __align__(16) float2 Bs[16][34];
  int tx = threadIdx.x, ty = threadIdx.y;
  int tid = ty * 16 + tx;
  int base = 5 - l;
  float2 c00 = {0.f,0.f}, c01 = {0.f,0.f}, c10 = {0.f,0.f}, c11 = {0.f,0.f};

  for (int kt = 0; kt < K; kt += 16) {
#pragma unroll
    for (int e = tid; e < 512; e += 256) {
      int i = e >> 4, kq = e & 15;
      int kc = kt + kq, row = row0 + i;
      float2 v = make_float2(0.f, 0.f);
      if (kc < K && row < R) {
        int b = row / D, mi = row - b*D;
        int ii = kc / D, ki = kc - ii*D;
        v = gX2[((b*FF1 + ii)*BB2 + l)*121 + (base + mi)*11 + (base + ki)];
      }
      As[i][kq] = v;
    }
#pragma unroll
    for (int e = tid; e < 512; e += 256) {
      int kq = e >> 5, j = e & 31;
      int kc = kt + kq, col = col0 + j;
      float2 v = make_float2(0.f, 0.f);
      if (kc < K && col < C) {
        int o = col / D, ni = col - o*D;
        int ii = kc / D, ki = kc - ii*D;
        v = gPSI2[((ii*FF2 + o)*BB2 + l)*121 + (base + ni)*11 + (base + ki)];
      }
      Bs[kq][j] = v;
    }
    __syncthreads();
#pragma unroll
    for (int kq = 0; kq < 16; ++kq) {
      float2 a0 = As[ty*2][kq];
      float2 a1 = As[ty*2 + 1][kq];
      float4 bb = *reinterpret_cast<const float4*>(&Bs[kq][tx*2]);
      c00.x += a0.x*bb.x + a0.y*bb.y;  c00.y += a0.y*bb.x - a0.x*bb.y;
      c01.x += a0.x*bb.z + a0.y*bb.w;  c01.y += a0.y*bb.z - a0.x*bb.w;
      c10.x += a1.x*bb.x + a1.y*bb.y;  c10.y += a1.y*bb.x - a1.x*bb.y;
      c11.x += a1.x*bb.z + a1.y*bb.w;  c11.y += a1.y*bb.z - a1.x*bb.w;
    }
    __syncthreads();
  }

  int r0 = row0 + ty*2, cc0 = col0 + tx*2;
#pragma unroll
  for (int dr = 0; dr < 2; ++dr) {
    int row = r0 + dr;
    if (row >= R) continue;
    int b = row / D, mi = row - b*D;
    float2 v0 = dr ? c10 : c00;
    float2 v1 = dr ? c11 : c01;
    if (cc0 < C) {
      int o = cc0 / D, ni = cc0 - o*D;
      gZ2[((b*FF2 + o)*BB2 + l)*121 + (base + mi)*11 + (base + ni)] = v0;
    }
    if (cc0 + 1 < C) {
      int o = (cc0+1) / D, ni = (cc0+1) - o*D;
      gZ2[((b*FF2 + o)*BB2 + l)*121 + (base + mi)*11 + (base + ni)] = v1;
    }
  }
}

// ---- fused stage 2 with hermitian symmetry: one block per (b,o) ----
__global__ __launch_bounds__(256) void k_fused2() {
  __shared__ float2 sZ[726];
  __shared__ float2 sFH2[792];    // [k][mi][n], m=5+mi
  __shared__ float2 sT2[864];     // [k][mi][g]
  __shared__ float2 sEA2[132];
  __shared__ float  sRed[256];

  int blk = blockIdx.x;
  int tid = threadIdx.x;

  for (int e = tid; e < 726; e += 256) sZ[e] = gZ2[(long)blk * 726 + e];
  for (int e = tid; e < 132; e += 256) sEA2[e] = gEA2[e];
  __syncthreads();

  for (int e = tid; e < 792; e += 256) {
    int k = e / 66, rem = e % 66;
    int mi = rem / 11, n = rem % 11;
    int an = n - 5; if (an < 0) an = -an;
    int lmin = mi > an ? mi : an;
    int mn = (5 + mi)*11 + n;
    float re = 0.f, im = 0.f;
    for (int l = lmin; l < BB2; ++l) {
      float w = gWINV2[(k*6 + l)*121 + mn];
      float2 z = sZ[l*121 + mn];
      re += w * z.x; im += w * z.y;
    }
    sFH2[e] = make_float2(re, im);
  }
  __syncthreads();

  for (int e = tid; e < 864; e += 256) {
    int k = e / 72, rem = e % 72;
    int mi = rem / 12, g = rem % 12;
    float re = 0.f, im = 0.f;
#pragma unroll
    for (int n = 0; n < 11; ++n) {
      float2 f = sFH2[(k*6 + mi)*11 + n];
      float2 ea = sEA2[n*12 + g];
      re += f.x * ea.x - f.y * ea.y;
      im += f.x * ea.y + f.y * ea.x;
    }
    sT2[e] = make_float2(re, im);
  }
  __syncthreads();

  float partial = 0.f;
  for (int e = tid; e < 1728; e += 256) {
    int k = e / 144, a = (e / 12) % 12, g = e % 12;
    float v = sT2[k*72 + g].x;
    float acc = 0.f;
#pragma unroll
    for (int mm = 1; mm < 6; ++mm) {
      float2 t = sT2[(k*6 + mm)*12 + g];
      float2 ea = sEA2[(5 + mm)*12 + a];
      acc += t.x * ea.x - t.y * ea.y;
    }
    v += 2.f * acc;
    if (v > 0.f) partial += v * gWINT[k];
  }
  sRed[tid] = partial;
  __syncthreads();
  for (int s = 128; s > 0; s >>= 1) {
    if (tid < s) sRed[tid] += sRed[tid + s];
    __syncthreads();
  }
  if (tid == 0) gFEAT[blk] = sRed[0] / 144.0f;
}

__global__ void k_out(const float* __restrict__ wl, const float* __restrict__ bl,
                      float* __restrict__ out) {
  int idx = blockIdx.x * blockDim.x + threadIdx.x;
  if (idx >= NB*FOUT) return;
  int f = idx % FOUT, b = idx / FOUT;
  float acc = bl[f];
#pragma unroll
  for (int o = 0; o < FF2; ++o) acc += gFEAT[b*FF2 + o] * wl[f*FF2 + o];
  out[idx] = acc;
}

extern "C" void kernel_launch(void* const* d_in, const int* in_sizes, int n_in,
                              void* d_out, int out_size) {
  const float* x  = (const float*)d_in[0];
  const float* k1 = (const float*)d_in[1];
  const float* k2 = (const float*)d_in[2];
  const float* wl = (const float*)d_in[3];
  const float* bl = (const float*)d_in[4];
  float* out = (float*)d_out;

  k_init_misc<<<7, 256>>>();
  k_init_wig<<<(10880 + 255) / 256, 256>>>();
  k_init_fill<<<(294624 + 255) / 256, 256>>>();

  k_x_part<<<NB*XCH, 192>>>(x);
  k_x_comb<<<(NB*190 + 255) / 256, 256>>>();
  k_psi<<<(FF1*BB1*MM1 + 255) / 256, 256>>>(k1);
  k_fused1<<<NB*FF1, 256>>>();
  k_psi2<<<dim3((726 + 31) / 32, (800 + 31) / 32), dim3(16, 16)>>>(k2);
  k_z2<<<dim3(14, 44, 6), dim3(16, 16)>>>();
  k_fused2<<<NB*FF2, 256>>>();
  k_out<<<(NB*FOUT + 255) / 256, 256>>>(wl, bl, out);
}

// round 7
// speedup vs baseline: 1.0390x; 1.0390x over previous
#include <cuda_runtime.h>
#include <math.h>

#define DPI 3.14159265358979323846

#define NB   128
#define NIN  30
#define BB1  10
#define MM1  19
#define NA1  20
#define FF1  20
#define BB2  6
#define MM2  11
#define NA2  12
#define FF2  40
#define FOUT 10
#define P1   24
#define P2   144

// ---- constant tables ----
__device__ float  gWS2F[BB1*MM1*NIN];
__device__ float2 gT1t[NIN*NIN*BB1*MM1];           // [kj][lm]
__device__ float2 gBS2[P1*BB1*MM1];
__device__ float  gWINV1[NA1*BB1*MM1*MM1];
__device__ float2 gEA1[MM1*NA1];
__device__ float  gWSO3[NA1*BB2*MM2*MM2];
__device__ float2 gF20[MM2*NA1];
__device__ float2 gBSO3[P2*BB2*MM2*MM2];
__device__ float  gWINV2[NA2*BB2*MM2*MM2];
__device__ float2 gEA2[MM2*NA2];
__device__ float  gWINT[NA2];

// ---- init helper tables ----
__device__ float  gQW15[30];
__device__ float  gQW10[20];
__device__ float2 gPA8[8*19];
__device__ float2 gPA8b[8*11];
__device__ float2 gPG6[6*11];
__device__ float2 gPH30[19*30];
__device__ float  gDS2G[3*10*10];
__device__ float  gDG3[3*6*121];

// ---- scratch ----
#define XCH 10
#define XLEN 90
__device__ float2 gXpart[XCH][NB*BB1*MM1];
__device__ float2 gX   [NB*BB1*MM1];
__device__ float2 gPSI [FF1*BB1*MM1];
__device__ float2 gYMN [NB*FF1*NA1*MM2*MM2];
__device__ float2 gX2  [NB*FF1*BB2*MM2*MM2];
__device__ float2 gPSI2[FF1*FF2*BB2*MM2*MM2];
__device__ float2 gZ2  [NB*FF2*BB2*MM2*MM2];       // invalid (l,m,n) stay 0 forever
__device__ float  gFEAT[NB*FF2];

__device__ __constant__ double c_fact[21] = {
  1.0, 1.0, 2.0, 6.0, 24.0, 120.0, 720.0, 5040.0, 40320.0, 362880.0,
  3628800.0, 39916800.0, 479001600.0, 6227020800.0, 87178291200.0,
  1307674368000.0, 20922789888000.0, 355687428096000.0,
  6402373705728000.0, 121645100408832000.0, 2432902008176640000.0 };

__device__ __forceinline__ double ipowd(double x, int e) {
  double r = 1.0;
  for (int i = 0; i < e; ++i) r *= x;
  return r;
}

__device__ double wigd(int l, int m, int n, double beta) {
  double cb = cos(0.5 * beta), sb = sin(0.5 * beta);
  double pref = sqrt(c_fact[l+m] * c_fact[l-m] * c_fact[l+n] * c_fact[l-n]);
  int s0 = (n - m > 0) ? (n - m) : 0;
  int s1 = (l + n < l - m) ? (l + n) : (l - m);
  double v = 0.0;
  for (int s = s0; s <= s1; ++s) {
    double t = 1.0 / (c_fact[l+n-s] * c_fact[s] * c_fact[m-n+s] * c_fact[l-m-s]);
    if ((m - n + s) & 1) t = -t;
    v += t * ipowd(cb, 2*l + n - m - 2*s) * ipowd(sb, m - n + 2*s);
  }
  return pref * v;
}

__device__ double quadw(int b, int k) {
  double beta = DPI * (2*k + 1) / (4.0 * b);
  double s = 0.0;
  for (int j = 0; j < b; ++j) s += sin((2*j + 1) * beta) / (2*j + 1);
  return 2.0 / b * sin(beta) * s;
}

// ======================= init kernels =======================
__global__ void k_init_misc() {
  const int TOT = 30 + 20 + 12 + 152 + 88 + 66 + 570 + 380 + 132 + 220;
  for (int idx = blockIdx.x * blockDim.x + threadIdx.x; idx < TOT;
       idx += gridDim.x * blockDim.x) {
    int r = idx;
    if (r < 30) { gQW15[r] = (float)quadw(15, r); continue; }
    r -= 30;
    if (r < 20) { gQW10[r] = (float)quadw(10, r); continue; }
    r -= 20;
    if (r < 12) { gWINT[r] = (float)quadw(6, r); continue; }
    r -= 12;
    if (r < 152) {
      int ia = r / 19, mp = r % 19 - 9;
      double ph = -(double)mp * (2.0 * DPI * ia / 8.0);
      double s, c; sincos(ph, &s, &c);
      gPA8[r] = make_float2((float)c, (float)s); continue;
    }
    r -= 152;
    if (r < 88) {
      int ia = r / 11, mp = r % 11 - 5;
      double ph = -(double)mp * (2.0 * DPI * ia / 8.0);
      double s, c; sincos(ph, &s, &c);
      gPA8b[r] = make_float2((float)c, (float)s); continue;
    }
    r -= 88;
    if (r < 66) {
      int ig = r / 11, np = r % 11 - 5;
      double ph = -(double)np * (2.0 * DPI * ig / 6.0);
      double s, c; sincos(ph, &s, &c);
      gPG6[r] = make_float2((float)c, (float)s); continue;
    }
    r -= 66;
    if (r < 570) {
      int mp = r / 30 - 9, j = r % 30;
      double ph = -2.0 * DPI * (double)mp * j / 30.0;
      double s, c; sincos(ph, &s, &c);
      gPH30[r] = make_float2((float)c, (float)s); continue;
    }
    r -= 570;
    if (r < 380) {
      int m = r / 20 - 9, a = r % 20;
      double ph = (double)m * 2.0 * DPI * a / 20.0;
      double s, c; sincos(ph, &s, &c);
      gEA1[r] = make_float2((float)c, (float)s); continue;
    }
    r -= 380;
    if (r < 132) {
      int m = r / 12 - 5, a = r % 12;
      double ph = (double)m * 2.0 * DPI * a / 12.0;
      double s, c; sincos(ph, &s, &c);
      gEA2[r] = make_float2((float)c, (float)s); continue;
    }
    r -= 132;
    {
      int mu = r / 20 - 5, a = r % 20;
      double ph = -2.0 * DPI * (double)mu * a / 20.0;
      double s, c; sincos(ph, &s, &c);
      gF20[r] = make_float2((float)c, (float)s);
    }
  }
}

__global__ void k_init_wig() {
  int idx = blockIdx.x * blockDim.x + threadIdx.x;
  if (idx < 1650) {
    int kb = idx / 55, j = idx % 55;
    int l = 0; while (j >= l + 1) { j -= l + 1; ++l; }
    int mm = j;
    double beta = DPI * (2*kb + 1) / 60.0;
    double v = wigd(l, mm, 0, beta) * (double)gQW15[kb];
    gWS2F[(l*19 + 9 + mm)*30 + kb] = (float)v;
    gWS2F[(l*19 + 9 - mm)*30 + kb] = (mm & 1) ? (float)(-v) : (float)v;
    return;
  }
  idx -= 1650;
  if (idx < 165) {
    int ib = idx / 55, j = idx % 55;
    int l = 0; while (j >= l + 1) { j -= l + 1; ++l; }
    int mm = j;
    double beta = (ib + 1) * DPI / 24.0;
    gDS2G[(ib*10 + l)*10 + mm] = (float)wigd(l, mm, 0, beta);
    return;
  }
  idx -= 165;
  if (idx < 7700) {
    int k = idx / 385, j = idx % 385;
    int l = 0; while (j >= (l+1)*(l+1)) { j -= (l+1)*(l+1); ++l; }
    int mm = (int)sqrtf((float)j);
    while (mm*mm > j) --mm;
    while ((mm+1)*(mm+1) <= j) ++mm;
    int nn = j - mm*mm - mm;
    double beta = DPI * (2*k + 1) / 40.0;
    float fv = (float)(wigd(l, mm, nn, beta) * (2*l + 1));
    float sv = ((mm - nn) & 1) ? -fv : fv;
    float* W = &gWINV1[(k*10 + l)*361];
    W[(9+mm)*19 + (9+nn)] = fv;
    W[(9+nn)*19 + (9+mm)] = sv;
    W[(9-mm)*19 + (9-nn)] = sv;
    W[(9-nn)*19 + (9-mm)] = fv;
    return;
  }
  idx -= 7700;
  if (idx < 1092) {
    int k = idx / 91, j = idx % 91;
    int l = 0; while (j >= (l+1)*(l+1)) { j -= (l+1)*(l+1); ++l; }
    int mm = (int)sqrtf((float)j);
    while (mm*mm > j) --mm;
    while ((mm+1)*(mm+1) <= j) ++mm;
    int nn = j - mm*mm - mm;
    double beta = DPI * (2*k + 1) / 24.0;
    float fv = (float)(wigd(l, mm, nn, beta) * (2*l + 1));
    float sv = ((mm - nn) & 1) ? -fv : fv;
    float* W = &gWINV2[(k*6 + l)*121];
    W[(5+mm)*11 + (5+nn)] = fv;
    W[(5+nn)*11 + (5+mm)] = sv;
    W[(5-mm)*11 + (5-nn)] = sv;
    W[(5-nn)*11 + (5-mm)] = fv;
    return;
  }
  idx -= 1092;
  if (idx < 273) {
    int ib = idx / 91, j = idx % 91;
    int l = 0; while (j >= (l+1)*(l+1)) { j -= (l+1)*(l+1); ++l; }
    int mm = (int)sqrtf((float)j);
    while (mm*mm > j) --mm;
    while ((mm+1)*(mm+1) <= j) ++mm;
    int nn = j - mm*mm - mm;
    double beta = (ib + 1) * DPI / 24.0;
    float fv = (float)wigd(l, mm, nn, beta);
    float sv = ((mm - nn) & 1) ? -fv : fv;
    float* W = &gDG3[(ib*6 + l)*121];
    W[(5+mm)*11 + (5+nn)] = fv;
    W[(5+nn)*11 + (5+mm)] = sv;
    W[(5-mm)*11 + (5-nn)] = sv;
    W[(5-nn)*11 + (5-mm)] = fv;
  }
}

__global__ void k_init_fill() {
  const int TOT = 4560 + 14520 + 104544 + 171000;
  for (int idx = blockIdx.x * blockDim.x + threadIdx.x; idx < TOT;
       idx += gridDim.x * blockDim.x) {
    int r = idx;
    if (r < 4560) {
      int p = r / 190, lm = r % 190, l = lm / 19, m = lm % 19, mp = m - 9;
      float2 v = make_float2(0.f, 0.f);
      if (abs(mp) <= l) {
        int ib = p / 8, ia = p % 8;
        float d;
        if (mp >= 0) d = gDS2G[(ib*10 + l)*10 + mp];
        else {
          d = gDS2G[(ib*10 + l)*10 - mp];
          if ((-mp) & 1) d = -d;
        }
        float2 ph = gPA8[ia*19 + 9 + mp];
        v = make_float2(d * ph.x, d * ph.y);
      }
      gBS2[r] = v; continue;
    }
    r -= 4560;
    if (r < 14520) {
      int k = r / 726, l = (r / 121) % 6, m = (r / 11) % 11, n = r % 11;
      float w = gWINV1[(k*10 + l)*361 + (m + 4)*19 + (n + 4)];
      gWSO3[r] = w * gQW10[k] / (float)(2*l + 1); continue;
    }
    r -= 14520;
    if (r < 104544) {
      int p = r / 726, l = (r / 121) % 6, m = (r / 11) % 11, n = r % 11;
      int ib = p / 48, ia = (p / 6) % 8, ig = p % 6;
      float d = gDG3[(ib*6 + l)*121 + m*11 + n];
      float2 pa = gPA8b[ia*11 + m], pg = gPG6[ig*11 + n];
      float2 ph = make_float2(pa.x*pg.x - pa.y*pg.y, pa.x*pg.y + pa.y*pg.x);
      gBSO3[r] = make_float2(d * ph.x, d * ph.y); continue;
    }
    r -= 104544;
    {
      int lm = r / 900, kj = r % 900;
      int k = kj / 30, j = kj % 30;
      int mp = (lm % 19) - 9;
      float w = gWS2F[lm*30 + k];
      float2 ph = gPH30[(mp + 9)*30 + j];
      gT1t[kj*190 + lm] = make_float2(w * ph.x, w * ph.y);
    }
  }
}

// ======================= pipeline =======================
__global__ void k_x_part(const float* __restrict__ x) {
  __shared__ float xs[XLEN];
  int blk = blockIdx.x;
  int c = blk % XCH, b = blk / XCH;
  for (int i = threadIdx.x; i < XLEN; i += blockDim.x) xs[i] = x[b*900 + c*XLEN + i];
  __syncthreads();
  int t = threadIdx.x;
  if (t < 190) {
    float re = 0.f, im = 0.f;
    const float2* T = &gT1t[c * XLEN * 190];
#pragma unroll 5
    for (int i = 0; i < XLEN; ++i) {
      float xv = xs[i];
      float2 w = T[i * 190 + t];
      re += xv * w.x; im += xv * w.y;
    }
    gXpart[c][b*190 + t] = make_float2(re, im);
  }
}

// combined: X reduction + psi
__global__ void k_comb_psi(const float* __restrict__ k1) {
  int idx = blockIdx.x * blockDim.x + threadIdx.x;
  if (idx < NB*190) {
    float re = 0.f, im = 0.f;
#pragma unroll
    for (int c = 0; c < XCH; ++c) {
      float2 v = gXpart[c][idx];
      re += v.x; im += v.y;
    }
    gX[idx] = make_float2(re, im);
    return;
  }
  idx -= NB*190;
  if (idx < FF1*190) {
    int lm = idx % 190, o = idx / 190;
    float re = 0.f, im = 0.f;
    for (int p = 0; p < P1; ++p) {
      float kv = k1[o*P1 + p];
      float2 bv = gBS2[p*190 + lm];
      re += kv * bv.x; im += kv * bv.y;
    }
    gPSI[idx] = make_float2(re, im);
  }
}

// ---- fused stage 1: 2 k-values per block, one block per (b,o,kpair) ----
__global__ __launch_bounds__(256) void k_fused1() {
  __shared__ float2 sX[190];
  __shared__ float2 sP[190];
  __shared__ float2 sEA1[380];
  __shared__ float2 sF20[220];
  __shared__ float2 sFH[380];   // [sk][mi][n]
  __shared__ float2 sT[400];    // [sk][mi][g]
  __shared__ float  sY[800];    // [sk][a][g]
  __shared__ float2 sU[240];    // [sk][r][g]

  int blk = blockIdx.x;                 // (b*FF1 + o)*10 + kp
  int kp = blk % 10;
  int bo = blk / 10;
  int o = bo % FF1, b = bo / FF1;
  int k0 = kp * 2;
  int tid = threadIdx.x;

  for (int e = tid; e < 190; e += 256) { sX[e] = gX[b*190 + e]; sP[e] = gPSI[o*190 + e]; }
  for (int e = tid; e < 380; e += 256) sEA1[e] = gEA1[e];
  for (int e = tid; e < 220; e += 256) sF20[e] = gF20[e];
  __syncthreads();

  // fh[sk][mi][n]
  for (int e = tid; e < 380; e += 256) {
    int sk = e / 190, r = e % 190;
    int mi = r / 19, n = r % 19;
    int an = n - 9; if (an < 0) an = -an;
    int lmin = mi > an ? mi : an;
    const float* W = &gWINV1[(k0 + sk) * BB1 * 361];
    int off = (9 + mi)*19 + n;
    float re = 0.f, im = 0.f;
    for (int l = lmin; l < BB1; ++l) {
      float w = W[l*361 + off];
      float2 xm = sX[l*19 + 9 + mi];
      float2 pe = sP[l*19 + n];
      re += w * (xm.x * pe.x + xm.y * pe.y);
      im += w * (xm.y * pe.x - xm.x * pe.y);
    }
    sFH[e] = make_float2(re, im);
  }
  __syncthreads();

  // t[sk][mi][g]
  for (int e = tid; e < 400; e += 256) {
    int sk = e / 200, r = e % 200;
    int mi = r / 20, g = r % 20;
    float re = 0.f, im = 0.f;
#pragma unroll
    for (int n = 0; n < 19; ++n) {
      float2 f = sFH[sk*190 + mi*19 + n];
      float2 ea = sEA1[n*20 + g];
      re += f.x * ea.x - f.y * ea.y;
      im += f.x * ea.y + f.y * ea.x;
    }
    sT[e] = make_float2(re, im);
  }
  __syncthreads();

  // y[sk][a][g]
  for (int e = tid; e < 800; e += 256) {
    int sk = e / 400, r = e % 400;
    int a = r / 20, g = r % 20;
    float v = sT[sk*200 + g].x;
    float acc = 0.f;
#pragma unroll
    for (int mm = 1; mm < 10; ++mm) {
      float2 t = sT[sk*200 + mm*20 + g];
      float2 ea = sEA1[(9 + mm)*20 + a];
      acc += t.x * ea.x - t.y * ea.y;
    }
    v += 2.f * acc;
    sY[e] = (v > 0.f) ? v : 0.f;
  }
  __syncthreads();

  // u[sk][r][g]
  for (int e = tid; e < 240; e += 256) {
    int sk = e / 120, rr = e % 120;
    int r = rr / 20, g = rr % 20;
    float re = 0.f, im = 0.f;
#pragma unroll
    for (int a = 0; a < 20; ++a) {
      float yv = sY[sk*400 + a*20 + g];
      float2 f = sF20[(5 + r)*20 + a];
      re += yv * f.x; im += yv * f.y;
    }
    sU[e] = make_float2(re, im);
  }
  __syncthreads();

  // ymn + hermitian mirror, write to gYMN
  for (int e = tid; e < 132; e += 256) {
    int sk = e / 66, rr = e % 66;
    int r = rr / 11, nu = rr % 11;
    float re = 0.f, im = 0.f;
#pragma unroll
    for (int g = 0; g < 20; ++g) {
      float2 u = sU[sk*120 + r*20 + g];
      float2 f = sF20[nu*20 + g];
      re += u.x * f.x - u.y * f.y;
      im += u.x * f.y + u.y * f.x;
    }
    long yb = ((long)bo * 20 + k0 + sk) * 121;
    gYMN[yb + (5 + r)*11 + nu] = make_float2(re, im);
    if (r > 0)
      gYMN[yb + (5 - r)*11 + (10 - nu)] = make_float2(re, -im);
  }
}

__global__ void k_x2() {
  int idx = blockIdx.x * blockDim.x + threadIdx.x;
  if (idx >= NB*FF1*BB2*121) return;
  int mn = idx % 121, l = (idx / 121) % 6, c = (idx / 726) % 20, b = idx / 14520;
  float re = 0.f, im = 0.f;
#pragma unroll
  for (int k = 0; k < 20; ++k) {
    float w = gWSO3[(k*6 + l)*121 + mn];
    float2 v = gYMN[((b*20 + c)*20 + k)*121 + mn];
    re += w * v.x; im += w * v.y;
  }
  gX2[idx] = make_float2(re, im);
}

// psi2 as real x complex GEMM: (800 x 144) x (144 x 726)
__global__ void k_psi2(const float* __restrict__ k2) {
  const int M = 800, N = 726, K = 144;
  __shared__ float As[32][17];
  __shared__ __align__(16) float2 Bs[16][34];
  int tx = threadIdx.x, ty = threadIdx.y;
  int tid = ty * 16 + tx;
  int row0 = blockIdx.y * 32, col0 = blockIdx.x * 32;
  float2 c00 = {0.f,0.f}, c01 = {0.f,0.f}, c10 = {0.f,0.f}, c11 = {0.f,0.f};

  for (int kt = 0; kt < K; kt += 16) {
#pragma unroll
    for (int e = tid; e < 512; e += 256) {
      int i = e >> 4, kq = e & 15;
      int row = row0 + i, kc = kt + kq;
      As[i][kq] = (row < M) ? k2[row*K + kc] : 0.f;
    }
#pragma unroll
    for (int e = tid; e < 512; e += 256) {
      int kq = e >> 5, j = e & 31;
      int kc = kt + kq, col = col0 + j;
      Bs[kq][j] = (col < N) ? gBSO3[kc*726 + col] : make_float2(0.f, 0.f);
    }
    __syncthreads();
#pragma unroll
    for (int kq = 0; kq < 16; ++kq) {
      float a0 = As[ty*2][kq];
      float a1 = As[ty*2 + 1][kq];
      float4 bb = *reinterpret_cast<const float4*>(&Bs[kq][tx*2]);
      c00.x += a0*bb.x; c00.y += a0*bb.y;
      c01.x += a0*bb.z; c01.y += a0*bb.w;
      c10.x += a1*bb.x; c10.y += a1*bb.y;
      c11.x += a1*bb.z; c11.y += a1*bb.w;
    }
    __syncthreads();
  }
  int r0 = row0 + ty*2, cc0 = col0 + tx*2;
  if (r0 < M) {
    if (cc0 < N)     gPSI2[r0*726 + cc0] = c00;
    if (cc0 + 1 < N) gPSI2[r0*726 + cc0 + 1] = c01;
  }
  if (r0 + 1 < M) {
    if (cc0 < N)     gPSI2[(r0+1)*726 + cc0] = c10;
    if (cc0 + 1 < N) gPSI2[(r0+1)*726 + cc0 + 1] = c11;
  }
}

// Z2 complex GEMM per l, compacted; 32x64 output tile, 2x4 register tile.
__global__ void k_z2() {
  int l = blockIdx.z;
  int D = 2*l + 1;
  int R = 128*D, C = 40*D, K = 20*D;
  int row0 = blockIdx.y * 32, col0 = blockIdx.x * 64;
  if (row0 >= R || col0 >= C) return;
  __shared__ __align__(16) float2 As[32][17];
  __shared__ __align__(16) float2 Bs[16][66];
  int tx = threadIdx.x, ty = threadIdx.y;
  int tid = ty * 16 + tx;
  int base = 5 - l;
  float2 acc[2][4];
#pragma unroll
  for (int i = 0; i < 2; ++i)
#pragma unroll
    for (int j = 0; j < 4; ++j) acc[i][j] = make_float2(0.f, 0.f);

  for (int kt = 0; kt < K; kt += 16) {
#pragma unroll
    for (int e = tid; e < 512; e += 256) {
      int i = e >> 4, kq = e & 15;
      int kc = kt + kq, row = row0 + i;
      float2 v = make_float2(0.f, 0.f);
      if (kc < K && row < R) {
        int b = row / D, mi = row - b*D;
        int ii = kc / D, ki = kc - ii*D;
        v = gX2[((b*FF1 + ii)*BB2 + l)*121 + (base + mi)*11 + (base + ki)];
      }
      As[i][kq] = v;
    }
#pragma unroll
    for (int e = tid; e < 1024; e += 256) {
      int kq = e >> 6, j = e & 63;
      int kc = kt + kq, col = col0 + j;
      float2 v = make_float2(0.f, 0.f);
      if (kc < K && col < C) {
        int o = col / D, ni = col - o*D;
        int ii = kc / D, ki = kc - ii*D;
        v = gPSI2[((ii*FF2 + o)*BB2 + l)*121 + (base + ni)*11 + (base + ki)];
      }
      Bs[kq][j] = v;
    }
    __syncthreads();
#pragma unroll
    for (int kq = 0; kq < 16; ++kq) {
      float2 a0 = As[ty*2][kq];
      float2 a1 = As[ty*2 + 1][kq];
      float4 b0 = *reinterpret_cast<const float4*>(&Bs[kq][tx*2]);
      float4 b1 = *reinterpret_cast<const float4*>(&Bs[kq][tx*2 + 32]);
      // acc += a * conj(b)
      acc[0][0].x += a0.x*b0.x + a0.y*b0.y;  acc[0][0].y += a0.y*b0.x - a0.x*b0.y;
      acc[0][1].x += a0.x*b0.z + a0.y*b0.w;  acc[0][1].y += a0.y*b0.z - a0.x*b0.w;
      acc[0][2].x += a0.x*b1.x + a0.y*b1.y;  acc[0][2].y += a0.y*b1.x - a0.x*b1.y;
      acc[0][3].x += a0.x*b1.z + a0.y*b1.w;  acc[0][3].y += a0.y*b1.z - a0.x*b1.w;
      acc[1][0].x += a1.x*b0.x + a1.y*b0.y;  acc[1][0].y += a1.y*b0.x - a1.x*b0.y;
      acc[1][1].x += a1.x*b0.z + a1.y*b0.w;  acc[1][1].y += a1.y*b0.z - a1.x*b0.w;
      acc[1][2].x += a1.x*b1.x + a1.y*b1.y;  acc[1][2].y += a1.y*b1.x - a1.x*b1.y;
      acc[1][3].x += a1.x*b1.z + a1.y*b1.w;  acc[1][3].y += a1.y*b1.z - a1.x*b1.w;
    }
    __syncthreads();
  }

  int r0 = row0 + ty*2;
  int cols[4] = { col0 + tx*2, col0 + tx*2 + 1, col0 + tx*2 + 32, col0 + tx*2 + 33 };
#pragma unroll
  for (int dr = 0; dr < 2; ++dr) {
    int row = r0 + dr;
    if (row >= R) continue;
    int b = row / D, mi = row - b*D;
#pragma unroll
    for (int dc = 0; dc < 4; ++dc) {
      int col = cols[dc];
      if (col >= C) continue;
      int o = col / D, ni = col - o*D;
      gZ2[((b*FF2 + o)*BB2 + l)*121 + (base + mi)*11 + (base + ni)] = acc[dr][dc];
    }
  }
}

// ---- fused stage 2 with hermitian symmetry: one block per (b,o) ----
__global__ __launch_bounds__(256) void k_fused2() {
  __shared__ float2 sZ[726];
  __shared__ float2 sFH2[792];
  __shared__ float2 sT2[864];
  __shared__ float2 sEA2[132];
  __shared__ float  sRed[256];

  int blk = blockIdx.x;
  int tid = threadIdx.x;

  for (int e = tid; e < 726; e += 256) sZ[e] = gZ2[(long)blk * 726 + e];
  for (int e = tid; e < 132; e += 256) sEA2[e] = gEA2[e];
  __syncthreads();

  for (int e = tid; e < 792; e += 256) {
    int k = e / 66, rem = e % 66;
    int mi = rem / 11, n = rem % 11;
    int an = n - 5; if (an < 0) an = -an;
    int lmin = mi > an ? mi : an;
    int mn = (5 + mi)*11 + n;
    float re = 0.f, im = 0.f;
    for (int l = lmin; l < BB2; ++l) {
      float w = gWINV2[(k*6 + l)*121 + mn];
      float2 z = sZ[l*121 + mn];
      re += w * z.x; im += w * z.y;
    }
    sFH2[e] = make_float2(re, im);
  }
  __syncthreads();

  for (int e = tid; e < 864; e += 256) {
    int k = e / 72, rem = e % 72;
    int mi = rem / 12, g = rem % 12;
    float re = 0.f, im = 0.f;
#pragma unroll
    for (int n = 0; n < 11; ++n) {
      float2 f = sFH2[(k*6 + mi)*11 + n];
      float2 ea = sEA2[n*12 + g];
      re += f.x * ea.x - f.y * ea.y;
      im += f.x * ea.y + f.y * ea.x;
    }
    sT2[e] = make_float2(re, im);
  }
  __syncthreads();

  float partial = 0.f;
  for (int e = tid; e < 1728; e += 256) {
    int k = e / 144, a = (e / 12) % 12, g = e % 12;
    float v = sT2[k*72 + g].x;
    float acc = 0.f;
#pragma unroll
    for (int mm = 1; mm < 6; ++mm) {
      float2 t = sT2[(k*6 + mm)*12 + g];
      float2 ea = sEA2[(5 + mm)*12 + a];
      acc += t.x * ea.x - t.y * ea.y;
    }
    v += 2.f * acc;
    if (v > 0.f) partial += v * gWINT[k];
  }
  sRed[tid] = partial;
  __syncthreads();
  for (int s = 128; s > 0; s >>= 1) {
    if (tid < s) sRed[tid] += sRed[tid + s];
    __syncthreads();
  }
  if (tid == 0) gFEAT[blk] = sRed[0] / 144.0f;
}

__global__ void k_out(const float* __restrict__ wl, const float* __restrict__ bl,
                      float* __restrict__ out) {
  int idx = blockIdx.x * blockDim.x + threadIdx.x;
  if (idx >= NB*FOUT) return;
  int f = idx % FOUT, b = idx / FOUT;
  float acc = bl[f];
#pragma unroll
  for (int o = 0; o < FF2; ++o) acc += gFEAT[b*FF2 + o] * wl[f*FF2 + o];
  out[idx] = acc;
}

extern "C" void kernel_launch(void* const* d_in, const int* in_sizes, int n_in,
                              void* d_out, int out_size) {
  const float* x  = (const float*)d_in[0];
  const float* k1 = (const float*)d_in[1];
  const float* k2 = (const float*)d_in[2];
  const float* wl = (const float*)d_in[3];
  const float* bl = (const float*)d_in[4];
  float* out = (float*)d_out;

  k_init_misc<<<7, 256>>>();
  k_init_wig<<<(10880 + 255) / 256, 256>>>();
  k_init_fill<<<(294624 + 255) / 256, 256>>>();

  k_x_part<<<NB*XCH, 192>>>(x);
  k_comb_psi<<<(NB*190 + FF1*190 + 255) / 256, 256>>>(k1);
  k_fused1<<<NB*FF1*10, 256>>>();
  k_x2 <<<(NB*FF1*BB2*121 + 255) / 256, 256>>>();
  k_psi2<<<dim3((726 + 31) / 32, (800 + 31) / 32), dim3(16, 16)>>>(k2);
  k_z2<<<dim3(7, 44, 6), dim3(16, 16)>>>();
  k_fused2<<<NB*FF2, 256>>>();
  k_out<<<(NB*FOUT + 255) / 256, 256>>>(wl, bl, out);
}

// round 9
// speedup vs baseline: 1.3508x; 1.3002x over previous
#include <cuda_runtime.h>
#include <math.h>

#define DPI 3.14159265358979323846

#define NB   128
#define NIN  30
#define BB1  10
#define MM1  19
#define NA1  20
#define FF1  20
#define BB2  6
#define MM2  11
#define NA2  12
#define FF2  40
#define FOUT 10
#define P1   24
#define P2   144

// ---- constant tables ----
__device__ float  gWS2F[BB1*MM1*NIN];
__device__ float2 gT1t[NIN*NIN*BB1*MM1];           // [kj][lm]
__device__ float2 gBS2[P1*BB1*MM1];
__device__ float  gWINV1[NA1*BB1*MM1*MM1];
__device__ float2 gEA1[MM1*NA1];
__device__ float  gWSO3[NA1*BB2*MM2*MM2];
__device__ float2 gF20[MM2*NA1];
__device__ float2 gBSO3[P2*BB2*MM2*MM2];
__device__ float  gWINV2[NA2*BB2*MM2*MM2];
__device__ float2 gEA2[MM2*NA2];
__device__ float  gWINT[NA2];

// ---- init helper tables ----
__device__ float  gQW15[30];
__device__ float  gQW10[20];
__device__ float2 gPA8[8*19];
__device__ float2 gPA8b[8*11];
__device__ float2 gPG6[6*11];
__device__ float2 gPH30[19*30];
__device__ float  gDS2G[3*10*10];
__device__ float  gDG3[3*6*121];

// ---- scratch ----
#define XCH 10
#define XLEN 90
__device__ float2 gXpart[XCH][NB*BB1*MM1];
__device__ float2 gX   [NB*BB1*MM1];
__device__ float2 gPSI [FF1*BB1*MM1];
__device__ float2 gYMN [NB*FF1*NA1*MM2*MM2];
__device__ float2 gX2  [NB*FF1*BB2*MM2*MM2];
__device__ float2 gPSI2[FF1*FF2*BB2*MM2*MM2];
__device__ float2 gZ2  [NB*FF2*BB2*MM2*MM2];       // invalid (l,m,n) stay 0 forever
__device__ float  gFEAT[NB*FF2];

__device__ __constant__ double c_fact[21] = {
  1.0, 1.0, 2.0, 6.0, 24.0, 120.0, 720.0, 5040.0, 40320.0, 362880.0,
  3628800.0, 39916800.0, 479001600.0, 6227020800.0, 87178291200.0,
  1307674368000.0, 20922789888000.0, 355687428096000.0,
  6402373705728000.0, 121645100408832000.0, 2432902008176640000.0 };

__device__ __forceinline__ double ipowd(double x, int e) {
  double r = 1.0;
  for (int i = 0; i < e; ++i) r *= x;
  return r;
}

__device__ double wigd(int l, int m, int n, double beta) {
  double cb = cos(0.5 * beta), sb = sin(0.5 * beta);
  double pref = sqrt(c_fact[l+m] * c_fact[l-m] * c_fact[l+n] * c_fact[l-n]);
  int s0 = (n - m > 0) ? (n - m) : 0;
  int s1 = (l + n < l - m) ? (l + n) : (l - m);
  double v = 0.0;
  for (int s = s0; s <= s1; ++s) {
    double t = 1.0 / (c_fact[l+n-s] * c_fact[s] * c_fact[m-n+s] * c_fact[l-m-s]);
    if ((m - n + s) & 1) t = -t;
    v += t * ipowd(cb, 2*l + n - m - 2*s) * ipowd(sb, m - n + 2*s);
  }
  return pref * v;
}

__device__ double quadw(int b, int k) {
  double beta = DPI * (2*k + 1) / (4.0 * b);
  double s = 0.0;
  for (int j = 0; j < b; ++j) s += sin((2*j + 1) * beta) / (2*j + 1);
  return 2.0 / b * sin(beta) * s;
}

// ======================= init kernels =======================
__global__ void k_init_misc() {
  const int TOT = 30 + 20 + 12 + 152 + 88 + 66 + 570 + 380 + 132 + 220;
  for (int idx = blockIdx.x * blockDim.x + threadIdx.x; idx < TOT;
       idx += gridDim.x * blockDim.x) {
    int r = idx;
    if (r < 30) { gQW15[r] = (float)quadw(15, r); continue; }
    r -= 30;
    if (r < 20) { gQW10[r] = (float)quadw(10, r); continue; }
    r -= 20;
    if (r < 12) { gWINT[r] = (float)quadw(6, r); continue; }
    r -= 12;
    if (r < 152) {
      int ia = r / 19, mp = r % 19 - 9;
      double ph = -(double)mp * (2.0 * DPI * ia / 8.0);
      double s, c; sincos(ph, &s, &c);
      gPA8[r] = make_float2((float)c, (float)s); continue;
    }
    r -= 152;
    if (r < 88) {
      int ia = r / 11, mp = r % 11 - 5;
      double ph = -(double)mp * (2.0 * DPI * ia / 8.0);
      double s, c; sincos(ph, &s, &c);
      gPA8b[r] = make_float2((float)c, (float)s); continue;
    }
    r -= 88;
    if (r < 66) {
      int ig = r / 11, np = r % 11 - 5;
      double ph = -(double)np * (2.0 * DPI * ig / 6.0);
      double s, c; sincos(ph, &s, &c);
      gPG6[r] = make_float2((float)c, (float)s); continue;
    }
    r -= 66;
    if (r < 570) {
      int mp = r / 30 - 9, j = r % 30;
      double ph = -2.0 * DPI * (double)mp * j / 30.0;
      double s, c; sincos(ph, &s, &c);
      gPH30[r] = make_float2((float)c, (float)s); continue;
    }
    r -= 570;
    if (r < 380) {
      int m = r / 20 - 9, a = r % 20;
      double ph = (double)m * 2.0 * DPI * a / 20.0;
      double s, c; sincos(ph, &s, &c);
      gEA1[r] = make_float2((float)c, (float)s); continue;
    }
    r -= 380;
    if (r < 132) {
      int m = r / 12 - 5, a = r % 12;
      double ph = (double)m * 2.0 * DPI * a / 12.0;
      double s, c; sincos(ph, &s, &c);
      gEA2[r] = make_float2((float)c, (float)s); continue;
    }
    r -= 132;
    {
      int mu = r / 20 - 5, a = r % 20;
      double ph = -2.0 * DPI * (double)mu * a / 20.0;
      double s, c; sincos(ph, &s, &c);
      gF20[r] = make_float2((float)c, (float)s);
    }
  }
}

__global__ void k_init_wig() {
  int idx = blockIdx.x * blockDim.x + threadIdx.x;
  if (idx < 1650) {
    int kb = idx / 55, j = idx % 55;
    int l = 0; while (j >= l + 1) { j -= l + 1; ++l; }
    int mm = j;
    double beta = DPI * (2*kb + 1) / 60.0;
    double v = wigd(l, mm, 0, beta) * (double)gQW15[kb];
    gWS2F[(l*19 + 9 + mm)*30 + kb] = (float)v;
    gWS2F[(l*19 + 9 - mm)*30 + kb] = (mm & 1) ? (float)(-v) : (float)v;
    return;
  }
  idx -= 1650;
  if (idx < 165) {
    int ib = idx / 55, j = idx % 55;
    int l = 0; while (j >= l + 1) { j -= l + 1; ++l; }
    int mm = j;
    double beta = (ib + 1) * DPI / 24.0;
    gDS2G[(ib*10 + l)*10 + mm] = (float)wigd(l, mm, 0, beta);
    return;
  }
  idx -= 165;
  if (idx < 7700) {
    int k = idx / 385, j = idx % 385;
    int l = 0; while (j >= (l+1)*(l+1)) { j -= (l+1)*(l+1); ++l; }
    int mm = (int)sqrtf((float)j);
    while (mm*mm > j) --mm;
    while ((mm+1)*(mm+1) <= j) ++mm;
    int nn = j - mm*mm - mm;
    double beta = DPI * (2*k + 1) / 40.0;
    float fv = (float)(wigd(l, mm, nn, beta) * (2*l + 1));
    float sv = ((mm - nn) & 1) ? -fv : fv;
    float* W = &gWINV1[(k*10 + l)*361];
    W[(9+mm)*19 + (9+nn)] = fv;
    W[(9+nn)*19 + (9+mm)] = sv;
    W[(9-mm)*19 + (9-nn)] = sv;
    W[(9-nn)*19 + (9-mm)] = fv;
    return;
  }
  idx -= 7700;
  if (idx < 1092) {
    int k = idx / 91, j = idx % 91;
    int l = 0; while (j >= (l+1)*(l+1)) { j -= (l+1)*(l+1); ++l; }
    int mm = (int)sqrtf((float)j);
    while (mm*mm > j) --mm;
    while ((mm+1)*(mm+1) <= j) ++mm;
    int nn = j - mm*mm - mm;
    double beta = DPI * (2*k + 1) / 24.0;
    float fv = (float)(wigd(l, mm, nn, beta) * (2*l + 1));
    float sv = ((mm - nn) & 1) ? -fv : fv;
    float* W = &gWINV2[(k*6 + l)*121];
    W[(5+mm)*11 + (5+nn)] = fv;
    W[(5+nn)*11 + (5+mm)] = sv;
    W[(5-mm)*11 + (5-nn)] = sv;
    W[(5-nn)*11 + (5-mm)] = fv;
    return;
  }
  idx -= 1092;
  if (idx < 273) {
    int ib = idx / 91, j = idx % 91;
    int l = 0; while (j >= (l+1)*(l+1)) { j -= (l+1)*(l+1); ++l; }
    int mm = (int)sqrtf((float)j);
    while (mm*mm > j) --mm;
    while ((mm+1)*(mm+1) <= j) ++mm;
    int nn = j - mm*mm - mm;
    double beta = (ib + 1) * DPI / 24.0;
    float fv = (float)wigd(l, mm, nn, beta);
    float sv = ((mm - nn) & 1) ? -fv : fv;
    float* W = &gDG3[(ib*6 + l)*121];
    W[(5+mm)*11 + (5+nn)] = fv;
    W[(5+nn)*11 + (5+mm)] = sv;
    W[(5-mm)*11 + (5-nn)] = sv;
    W[(5-nn)*11 + (5-mm)] = fv;
  }
}

__global__ void k_init_fill() {
  const int TOT = 4560 + 14520 + 104544 + 171000;
  for (int idx = blockIdx.x * blockDim.x + threadIdx.x; idx < TOT;
       idx += gridDim.x * blockDim.x) {
    int r = idx;
    if (r < 4560) {
      int p = r / 190, lm = r % 190, l = lm / 19, m = lm % 19, mp = m - 9;
      float2 v = make_float2(0.f, 0.f);
      if (abs(mp) <= l) {
        int ib = p / 8, ia = p % 8;
        float d;
        if (mp >= 0) d = gDS2G[(ib*10 + l)*10 + mp];
        else {
          d = gDS2G[(ib*10 + l)*10 - mp];
          if ((-mp) & 1) d = -d;
        }
        float2 ph = gPA8[ia*19 + 9 + mp];
        v = make_float2(d * ph.x, d * ph.y);
      }
      gBS2[r] = v; continue;
    }
    r -= 4560;
    if (r < 14520) {
      int k = r / 726, l = (r / 121) % 6, m = (r / 11) % 11, n = r % 11;
      float w = gWINV1[(k*10 + l)*361 + (m + 4)*19 + (n + 4)];
      gWSO3[r] = w * gQW10[k] / (float)(2*l + 1); continue;
    }
    r -= 14520;
    if (r < 104544) {
      int p = r / 726, l = (r / 121) % 6, m = (r / 11) % 11, n = r % 11;
      int ib = p / 48, ia = (p / 6) % 8, ig = p % 6;
      float d = gDG3[(ib*6 + l)*121 + m*11 + n];
      float2 pa = gPA8b[ia*11 + m], pg = gPG6[ig*11 + n];
      float2 ph = make_float2(pa.x*pg.x - pa.y*pg.y, pa.x*pg.y + pa.y*pg.x);
      gBSO3[r] = make_float2(d * ph.x, d * ph.y); continue;
    }
    r -= 104544;
    {
      int lm = r / 900, kj = r % 900;
      int k = kj / 30, j = kj % 30;
      int mp = (lm % 19) - 9;
      float w = gWS2F[lm*30 + k];
      float2 ph = gPH30[(mp + 9)*30 + j];
      gT1t[kj*190 + lm] = make_float2(w * ph.x, w * ph.y);
    }
  }
}

// ======================= pipeline =======================
__global__ void k_x_part(const float* __restrict__ x) {
  __shared__ float xs[XLEN];
  int blk = blockIdx.x;
  int c = blk % XCH, b = blk / XCH;
  for (int i = threadIdx.x; i < XLEN; i += blockDim.x) xs[i] = x[b*900 + c*XLEN + i];
  __syncthreads();
  int t = threadIdx.x;
  if (t < 190) {
    float re = 0.f, im = 0.f;
    const float2* T = &gT1t[c * XLEN * 190];
#pragma unroll 5
    for (int i = 0; i < XLEN; ++i) {
      float xv = xs[i];
      float2 w = T[i * 190 + t];
      re += xv * w.x; im += xv * w.y;
    }
    gXpart[c][b*190 + t] = make_float2(re, im);
  }
}

__global__ void k_comb_psi(const float* __restrict__ k1) {
  int idx = blockIdx.x * blockDim.x + threadIdx.x;
  if (idx < NB*190) {
    float re = 0.f, im = 0.f;
#pragma unroll
    for (int c = 0; c < XCH; ++c) {
      float2 v = gXpart[c][idx];
      re += v.x; im += v.y;
    }
    gX[idx] = make_float2(re, im);
    return;
  }
  idx -= NB*190;
  if (idx < FF1*190) {
    int lm = idx % 190, o = idx / 190;
    float re = 0.f, im = 0.f;
    for (int p = 0; p < P1; ++p) {
      float kv = k1[o*P1 + p];
      float2 bv = gBS2[p*190 + lm];
      re += kv * bv.x; im += kv * bv.y;
    }
    gPSI[idx] = make_float2(re, im);
  }
}

// ---- fused stage 1: 2 k-values per block; half-period DFT folding ----
__global__ __launch_bounds__(256) void k_fused1() {
  __shared__ float2 sX[190];
  __shared__ float2 sP[190];
  __shared__ float2 sEA1[380];
  __shared__ float2 sF20[220];
  __shared__ float2 sFH[380];   // [sk][mi][n]
  __shared__ float2 sT[400];    // [sk][mi][g]
  __shared__ float  sY[800];    // [sk]: rows 0-9 = ys(a), rows 10-19 = yd(a)
  __shared__ float2 sU[240];    // [sk][r][g]

  int blk = blockIdx.x;                 // (b*FF1 + o)*10 + kp
  int kp = blk % 10;
  int bo = blk / 10;
  int o = bo % FF1, b = bo / FF1;
  int k0 = kp * 2;
  int tid = threadIdx.x;

  for (int e = tid; e < 190; e += 256) { sX[e] = gX[b*190 + e]; sP[e] = gPSI[o*190 + e]; }
  for (int e = tid; e < 380; e += 256) sEA1[e] = gEA1[e];
  for (int e = tid; e < 220; e += 256) sF20[e] = gF20[e];
  __syncthreads();

  // fh[sk][mi][n]
  for (int e = tid; e < 380; e += 256) {
    int sk = e / 190, r = e % 190;
    int mi = r / 19, n = r % 19;
    int an = n - 9; if (an < 0) an = -an;
    int lmin = mi > an ? mi : an;
    const float* W = &gWINV1[(k0 + sk) * BB1 * 361];
    int off = (9 + mi)*19 + n;
    float re = 0.f, im = 0.f;
    for (int l = lmin; l < BB1; ++l) {
      float w = W[l*361 + off];
      float2 xm = sX[l*19 + 9 + mi];
      float2 pe = sP[l*19 + n];
      re += w * (xm.x * pe.x + xm.y * pe.y);
      im += w * (xm.y * pe.x - xm.x * pe.y);
    }
    sFH[e] = make_float2(re, im);
  }
  __syncthreads();

  // t[sk][mi][g] with half-period fold: pair (g, g+10)
  for (int e = tid; e < 200; e += 256) {
    int sk = e / 100, rr = e % 100;
    int mi = rr / 10, g = rr % 10;
    float sex = 0.f, sey = 0.f, sox = 0.f, soy = 0.f;
#pragma unroll
    for (int n = 0; n < 19; ++n) {
      float2 f = sFH[sk*190 + mi*19 + n];
      float2 ea = sEA1[n*20 + g];
      float tx = f.x * ea.x - f.y * ea.y;
      float ty = f.x * ea.y + f.y * ea.x;
      if (n & 1) { sex += tx; sey += ty; }
      else       { sox += tx; soy += ty; }
    }
    sT[sk*200 + mi*20 + g]      = make_float2(sex + sox, sey + soy);
    sT[sk*200 + mi*20 + g + 10] = make_float2(sex - sox, sey - soy);
  }
  __syncthreads();

  // y pairs (a, a+10)
  for (int e = tid; e < 400; e += 256) {
    int sk = e / 200, rr = e % 200;
    int a = rr / 20, g = rr % 20;   // a in 0..9
    float t0 = sT[sk*200 + g].x;
    float se = 0.f, so = 0.f;
#pragma unroll
    for (int mm = 1; mm < 10; ++mm) {
      float2 t = sT[sk*200 + mm*20 + g];
      float2 ea = sEA1[(9 + mm)*20 + a];
      float v = t.x * ea.x - t.y * ea.y;
      if (mm & 1) so += v; else se += v;
    }
    float y1 = t0 + 2.f * (se + so);
    float y2v = t0 + 2.f * (se - so);
    y1 = (y1 > 0.f) ? y1 : 0.f;
    y2v = (y2v > 0.f) ? y2v : 0.f;
    sY[sk*400 + a*20 + g]        = y1 + y2v;   // ys
    sY[sk*400 + (a+10)*20 + g]   = y1 - y2v;   // yd
  }
  __syncthreads();

  // u[sk][r][g]
  for (int e = tid; e < 240; e += 256) {
    int sk = e / 120, rr = e % 120;
    int r = rr / 20, g = rr % 20;
    const float* yb = &sY[sk*400 + ((r & 1) ? 200 : 0)];
    float re = 0.f, im = 0.f;
#pragma unroll
    for (int a = 0; a < 10; ++a) {
      float yv = yb[a*20 + g];
      float2 f = sF20[(5 + r)*20 + a];
      re += yv * f.x; im += yv * f.y;
    }
    sU[e] = make_float2(re, im);
  }
  __syncthreads();

  // ymn: fold over g pairs (g, g+10)
  for (int e = tid; e < 132; e += 256) {
    int sk = e / 66, rr = e % 66;
    int r = rr / 11, nu = rr % 11;
    float sgn = (nu & 1) ? 1.f : -1.f;
    float re = 0.f, im = 0.f;
#pragma unroll
    for (int g = 0; g < 10; ++g) {
      float2 u1 = sU[sk*120 + r*20 + g];
      float2 u2 = sU[sk*120 + r*20 + g + 10];
      float ux = u1.x + sgn * u2.x;
      float uy = u1.y + sgn * u2.y;
      float2 f = sF20[nu*20 + g];
      re += ux * f.x - uy * f.y;
      im += ux * f.y + uy * f.x;
    }
    long yb = ((long)bo * 20 + k0 + sk) * 121;
    gYMN[yb + (5 + r)*11 + nu] = make_float2(re, im);
    if (r > 0)
      gYMN[yb + (5 - r)*11 + (10 - nu)] = make_float2(re, -im);
  }
}

__global__ void k_x2() {
  int idx = blockIdx.x * blockDim.x + threadIdx.x;
  if (idx >= NB*FF1*BB2*121) return;
  int mn = idx % 121, l = (idx / 121) % 6, c = (idx / 726) % 20, b = idx / 14520;
  float re = 0.f, im = 0.f;
#pragma unroll
  for (int k = 0; k < 20; ++k) {
    float w = gWSO3[(k*6 + l)*121 + mn];
    float2 v = gYMN[((b*20 + c)*20 + k)*121 + mn];
    re += w * v.x; im += w * v.y;
  }
  gX2[idx] = make_float2(re, im);
}

// psi2 as real x complex GEMM: (800 x 144) x (144 x 726)
__global__ void k_psi2(const float* __restrict__ k2) {
  const int M = 800, N = 726, K = 144;
  __shared__ float As[32][17];
  __shared__ __align__(16) float2 Bs[16][34];
  int tx = threadIdx.x, ty = threadIdx.y;
  int tid = ty * 16 + tx;
  int row0 = blockIdx.y * 32, col0 = blockIdx.x * 32;
  float2 c00 = {0.f,0.f}, c01 = {0.f,0.f}, c10 = {0.f,0.f}, c11 = {0.f,0.f};

  for (int kt = 0; kt < K; kt += 16) {
#pragma unroll
    for (int e = tid; e < 512; e += 256) {
      int i = e >> 4, kq = e & 15;
      int row = row0 + i, kc = kt + kq;
      As[i][kq] = (row < M) ? k2[row*K + kc] : 0.f;
    }
#pragma unroll
    for (int e = tid; e < 512; e += 256) {
      int kq = e >> 5, j = e & 31;
      int kc = kt + kq, col = col0 + j;
      Bs[kq][j] = (col < N) ? gBSO3[kc*726 + col] : make_float2(0.f, 0.f);
    }
    __syncthreads();
#pragma unroll
    for (int kq = 0; kq < 16; ++kq) {
      float a0 = As[ty*2][kq];
      float a1 = As[ty*2 + 1][kq];
      float4 bb = *reinterpret_cast<const float4*>(&Bs[kq][tx*2]);
      c00.x += a0*bb.x; c00.y += a0*bb.y;
      c01.x += a0*bb.z; c01.y += a0*bb.w;
      c10.x += a1*bb.x; c10.y += a1*bb.y;
      c11.x += a1*bb.z; c11.y += a1*bb.w;
    }
    __syncthreads();
  }
  int r0 = row0 + ty*2, cc0 = col0 + tx*2;
  if (r0 < M) {
    if (cc0 < N)     gPSI2[r0*726 + cc0] = c00;
    if (cc0 + 1 < N) gPSI2[r0*726 + cc0 + 1] = c01;
  }
  if (r0 + 1 < M) {
    if (cc0 < N)     gPSI2[(r0+1)*726 + cc0] = c10;
    if (cc0 + 1 < N) gPSI2[(r0+1)*726 + cc0 + 1] = c11;
  }
}

// Z2 complex GEMM per l; 32x64 tile, 2x4 reg tile; smem addr LUTs
__global__ void k_z2() {
  int l = blockIdx.z;
  int D = 2*l + 1;
  int R = 128*D, C = 40*D, K = 20*D;
  int row0 = blockIdx.y * 32, col0 = blockIdx.x * 64;
  if (row0 >= R || col0 >= C) return;
  __shared__ __align__(16) float2 As[32][17];
  __shared__ __align__(16) float2 Bs[16][66];
  __shared__ int sRA[32];    // A-load row partial (gX2)
  __shared__ int sCB[64];    // B-load col partial (gPSI2)
  __shared__ int sRO[32];    // OUT row partial (gZ2)
  __shared__ int sCO[64];    // OUT col partial (gZ2)
  __shared__ int sKA[220];
  __shared__ int sKB[220];
  int tx = threadIdx.x, ty = threadIdx.y;
  int tid = ty * 16 + tx;
  int base = 5 - l;
  int L0 = l*121 + base*12;

  for (int e = tid; e < 32; e += 256) {
    int row = row0 + e;
    if (row < R) {
      int b = row / D, mi = row - b*D;
      sRA[e] = b*14520 + mi*11 + L0;
      sRO[e] = b*29040 + mi*11 + L0;
    } else { sRA[e] = -1; sRO[e] = -1; }
  }
  for (int e = tid; e < 64; e += 256) {
    int col = col0 + e;
    if (col < C) {
      int o = col / D, ni = col - o*D;
      sCB[e] = o*726 + ni*11 + L0;
      sCO[e] = o*726 + ni;
    } else { sCB[e] = -1; sCO[e] = -1; }
  }
  for (int e = tid; e < K; e += 256) {
    int ii = e / D, ki = e - ii*D;
    sKA[e] = ii*726 + ki;
    sKB[e] = ii*29040 + ki;
  }
  __syncthreads();

  float2 acc[2][4];
#pragma unroll
  for (int i = 0; i < 2; ++i)
#pragma unroll
    for (int j = 0; j < 4; ++j) acc[i][j] = make_float2(0.f, 0.f);

  for (int kt = 0; kt < K; kt += 16) {
#pragma unroll
    for (int e = tid; e < 512; e += 256) {
      int i = e >> 4, kq = e & 15;
      int kc = kt + kq;
      float2 v = make_float2(0.f, 0.f);
      if (kc < K && sRA[i] >= 0) v = gX2[sRA[i] + sKA[kc]];
      As[i][kq] = v;
    }
#pragma unroll
    for (int e = tid; e < 1024; e += 256) {
      int kq = e >> 6, j = e & 63;
      int kc = kt + kq;
      float2 v = make_float2(0.f, 0.f);
      if (kc < K && sCB[j] >= 0) v = gPSI2[sCB[j] + sKB[kc]];
      Bs[kq][j] = v;
    }
    __syncthreads();
#pragma unroll
    for (int kq = 0; kq < 16; ++kq) {
      float2 a0 = As[ty*2][kq];
      float2 a1 = As[ty*2 + 1][kq];
      float4 b0 = *reinterpret_cast<const float4*>(&Bs[kq][tx*2]);
      float4 b1 = *reinterpret_cast<const float4*>(&Bs[kq][tx*2 + 32]);
      acc[0][0].x += a0.x*b0.x + a0.y*b0.y;  acc[0][0].y += a0.y*b0.x - a0.x*b0.y;
      acc[0][1].x += a0.x*b0.z + a0.y*b0.w;  acc[0][1].y += a0.y*b0.z - a0.x*b0.w;
      acc[0][2].x += a0.x*b1.x + a0.y*b1.y;  acc[0][2].y += a0.y*b1.x - a0.x*b1.y;
      acc[0][3].x += a0.x*b1.z + a0.y*b1.w;  acc[0][3].y += a0.y*b1.z - a0.x*b1.w;
      acc[1][0].x += a1.x*b0.x + a1.y*b0.y;  acc[1][0].y += a1.y*b0.x - a1.x*b0.y;
      acc[1][1].x += a1.x*b0.z + a1.y*b0.w;  acc[1][1].y += a1.y*b0.z - a1.x*b0.w;
      acc[1][2].x += a1.x*b1.x + a1.y*b1.y;  acc[1][2].y += a1.y*b1.x - a1.x*b1.y;
      acc[1][3].x += a1.x*b1.z + a1.y*b1.w;  acc[1][3].y += a1.y*b1.z - a1.x*b1.w;
    }
    __syncthreads();
  }

  int ir0 = ty*2;
  int jc[4] = { tx*2, tx*2 + 1, tx*2 + 32, tx*2 + 33 };
#pragma unroll
  for (int dr = 0; dr < 2; ++dr) {
    int ro = sRO[ir0 + dr];
    if (ro < 0) continue;
#pragma unroll
    for (int dc = 0; dc < 4; ++dc) {
      int co = sCO[jc[dc]];
      if (co < 0) continue;
      gZ2[ro + co] = acc[dr][dc];
    }
  }
}

// ---- fused stage 2 with hermitian symmetry + half-period folds ----
__global__ __launch_bounds__(256) void k_fused2() {
  __shared__ float2 sZ[726];
  __shared__ float2 sFH2[792];
  __shared__ float2 sT2[864];
  __shared__ float2 sEA2[132];
  __shared__ float  sRed[256];

  int blk = blockIdx.x;
  int tid = threadIdx.x;

  for (int e = tid; e < 726; e += 256) sZ[e] = gZ2[(long)blk * 726 + e];
  for (int e = tid; e < 132; e += 256) sEA2[e] = gEA2[e];
  __syncthreads();

  for (int e = tid; e < 792; e += 256) {
    int k = e / 66, rem = e % 66;
    int mi = rem / 11, n = rem % 11;
    int an = n - 5; if (an < 0) an = -an;
    int lmin = mi > an ? mi : an;
    int mn = (5 + mi)*11 + n;
    float re = 0.f, im = 0.f;
    for (int l = lmin; l < BB2; ++l) {
      float w = gWINV2[(k*6 + l)*121 + mn];
      float2 z = sZ[l*121 + mn];
      re += w * z.x; im += w * z.y;
    }
    sFH2[e] = make_float2(re, im);
  }
  __syncthreads();

  // t2 with fold: pairs (g, g+6)
  for (int e = tid; e < 432; e += 256) {
    int k = e / 36, rr = e % 36;
    int mi = rr / 6, g = rr % 6;
    float sex = 0.f, sey = 0.f, sox = 0.f, soy = 0.f;
#pragma unroll
    for (int n = 0; n < 11; ++n) {
      float2 f = sFH2[(k*6 + mi)*11 + n];
      float2 ea = sEA2[n*12 + g];
      float tx = f.x * ea.x - f.y * ea.y;
      float ty = f.x * ea.y + f.y * ea.x;
      if (n & 1) { sex += tx; sey += ty; }
      else       { sox += tx; soy += ty; }
    }
    sT2[(k*6 + mi)*12 + g]     = make_float2(sex + sox, sey + soy);
    sT2[(k*6 + mi)*12 + g + 6] = make_float2(sex - sox, sey - soy);
  }
  __syncthreads();

  // y2 pairs (a, a+6)
  float partial = 0.f;
  for (int e = tid; e < 864; e += 256) {
    int k = e / 72, rr = e % 72;
    int a = rr / 12, g = rr % 12;
    float t0 = sT2[k*72 + g].x;
    float se = 0.f, so = 0.f;
#pragma unroll
    for (int mm = 1; mm < 6; ++mm) {
      float2 t = sT2[(k*6 + mm)*12 + g];
      float2 ea = sEA2[(5 + mm)*12 + a];
      float v = t.x * ea.x - t.y * ea.y;
      if (mm & 1) so += v; else se += v;
    }
    float v1 = t0 + 2.f * (se + so);
    float v2 = t0 + 2.f * (se - so);
    v1 = (v1 > 0.f) ? v1 : 0.f;
    v2 = (v2 > 0.f) ? v2 : 0.f;
    partial += (v1 + v2) * gWINT[k];
  }
  sRed[tid] = partial;
  __syncthreads();
  for (int s = 128; s > 0; s >>= 1) {
    if (tid < s) sRed[tid] += sRed[tid + s];
    __syncthreads();
  }
  if (tid == 0) gFEAT[blk] = sRed[0] / 144.0f;
}

__global__ void k_out(const float* __restrict__ wl, const float* __restrict__ bl,
                      float* __restrict__ out) {
  int idx = blockIdx.x * blockDim.x + threadIdx.x;
  if (idx >= NB*FOUT) return;
  int f = idx % FOUT, b = idx / FOUT;
  float acc = bl[f];
#pragma unroll
  for (int o = 0; o < FF2; ++o) acc += gFEAT[b*FF2 + o] * wl[f*FF2 + o];
  out[idx] = acc;
}

extern "C" void kernel_launch(void* const* d_in, const int* in_sizes, int n_in,
                              void* d_out, int out_size) {
  const float* x  = (const float*)d_in[0];
  const float* k1 = (const float*)d_in[1];
  const float* k2 = (const float*)d_in[2];
  const float* wl = (const float*)d_in[3];
  const float* bl = (const float*)d_in[4];
  float* out = (float*)d_out;

  k_init_misc<<<7, 256>>>();
  k_init_wig<<<(10880 + 255) / 256, 256>>>();
  k_init_fill<<<(294624 + 255) / 256, 256>>>();

  k_x_part<<<NB*XCH, 192>>>(x);
  k_comb_psi<<<(NB*190 + FF1*190 + 255) / 256, 256>>>(k1);
  k_fused1<<<NB*FF1*10, 256>>>();
  k_x2 <<<(NB*FF1*BB2*121 + 255) / 256, 256>>>();
  k_psi2<<<dim3((726 + 31) / 32, (800 + 31) / 32), dim3(16, 16)>>>(k2);
  k_z2<<<dim3(7, 44, 6), dim3(16, 16)>>>();
  k_fused2<<<NB*FF2, 256>>>();
  k_out<<<(NB*FOUT + 255) / 256, 256>>>(wl, bl, out);
}